// round 1
// baseline (speedup 1.0000x reference)
#include <cuda_runtime.h>
#include <cuda_bf16.h>

#define NB   8
#define LSEQ 256
#define D1   512
#define D2   512
#define DK   64
#define NCOL (DK * D2)   // 32768

// 32 MB scratch: tmp[i][k][q] for one batch b
__device__ float g_tmp[(size_t)LSEQ * DK * D2];

// ---------------------------------------------------------------------------
// Stage 1: tmp[i, k, q] = sum_p x1[i, p] * W[k, p, q]   (one batch b)
// GEMM: C[M=256][N=32768] = A[256][512] * Bm[512][32768]
// Block tile 128(m) x 64(n), kc=16, 256 threads, 8x4 outputs/thread.
// ---------------------------------------------------------------------------
__global__ void __launch_bounds__(256) stage1_kernel(
    const float* __restrict__ x1,   // [LSEQ, D1] for this b
    const float* __restrict__ w,    // [DK, D1, D2]
    float* __restrict__ tmp)        // [LSEQ, NCOL]
{
    __shared__ float As[16][132];   // [p][m], padded
    __shared__ float Bs[16][68];    // [p][n], padded

    const int n0 = blockIdx.x * 64;     // 0..32704
    const int m0 = blockIdx.y * 128;    // 0 or 128
    const int k  = n0 >> 9;             // output feature (n-tile lies in one k)
    const int q0 = n0 & 511;

    const int t  = threadIdx.x;
    const int tx = t & 15;              // n = tx*4
    const int ty = t >> 4;              // m = ty*8

    const float* Ap = x1 + (size_t)m0 * D1;
    const float* Bp = w + (size_t)k * (D1 * D2) + q0;

    float acc[8][4];
#pragma unroll
    for (int i = 0; i < 8; i++)
#pragma unroll
        for (int j = 0; j < 4; j++) acc[i][j] = 0.f;

    for (int p0 = 0; p0 < D1; p0 += 16) {
        // A tile: 128(m) x 16(p) -> As[p][m] (transposed)
#pragma unroll
        for (int i = 0; i < 8; i++) {
            int idx = t + i * 256;
            int m = idx >> 4, p = idx & 15;
            As[p][m] = Ap[(size_t)m * D1 + p0 + p];
        }
        // B tile: 16(p) x 64(n) -> Bs[p][n]
#pragma unroll
        for (int i = 0; i < 4; i++) {
            int idx = t + i * 256;
            int p = idx >> 6, n = idx & 63;
            Bs[p][n] = Bp[(size_t)(p0 + p) * D2 + n];
        }
        __syncthreads();
#pragma unroll
        for (int kk = 0; kk < 16; kk++) {
            float4 a0 = *(const float4*)&As[kk][ty * 8];
            float4 a1 = *(const float4*)&As[kk][ty * 8 + 4];
            float4 b  = *(const float4*)&Bs[kk][tx * 4];
            float av[8] = {a0.x, a0.y, a0.z, a0.w, a1.x, a1.y, a1.z, a1.w};
            float bv[4] = {b.x, b.y, b.z, b.w};
#pragma unroll
            for (int i = 0; i < 8; i++)
#pragma unroll
                for (int j = 0; j < 4; j++) acc[i][j] += av[i] * bv[j];
        }
        __syncthreads();
    }

#pragma unroll
    for (int r = 0; r < 8; r++) {
        int m = m0 + ty * 8 + r;
        float4 v = make_float4(acc[r][0], acc[r][1], acc[r][2], acc[r][3]);
        *(float4*)&tmp[(size_t)m * NCOL + n0 + tx * 4] = v;
    }
}

// ---------------------------------------------------------------------------
// Stage 2: out[i, j, k] = sum_q tmp[i, k, q] * x2[j, q] + bias[k]  (one batch)
// Per block: fixed i, j-tile of 128, all k=64. A=tmp[i] [64k x 512q],
// B=x2 [256j x 512q], both reduce over contiguous q (A @ B^T).
// 256 threads: tk=t&15 -> k=tk*4 (float4), tj=t>>4 -> j=tj*8. 8x4 acc/thread.
// Epilogue: half-warp writes 64 contiguous k floats per j (coalesced float4).
// ---------------------------------------------------------------------------
__global__ void __launch_bounds__(256) stage2_kernel(
    const float* __restrict__ tmp,   // [LSEQ(i), DK, D2]
    const float* __restrict__ x2,    // [LSEQ(j), D2] for this b
    const float* __restrict__ bias,  // [DK]
    float* __restrict__ out)         // [LSEQ(i), LSEQ(j), DK] for this b
{
    __shared__ float As[16][68];     // [q][k]
    __shared__ float Bs[16][132];    // [q][j]

    const int i  = blockIdx.y;
    const int j0 = blockIdx.x * 128;

    const int t  = threadIdx.x;
    const int tk = t & 15;           // k = tk*4
    const int tj = t >> 4;           // j = j0 + tj*8

    const float* Ap = tmp + (size_t)i * (DK * D2);
    const float* Bp = x2 + (size_t)j0 * D2;

    float acc[8][4];
#pragma unroll
    for (int a = 0; a < 8; a++)
#pragma unroll
        for (int c = 0; c < 4; c++) acc[a][c] = 0.f;

    for (int q0 = 0; q0 < D2; q0 += 16) {
        // A tile: 64(k) x 16(q) -> As[q][k]
#pragma unroll
        for (int ii = 0; ii < 4; ii++) {
            int idx = t + ii * 256;
            int kr = idx >> 4, q = idx & 15;
            As[q][kr] = Ap[(size_t)kr * D2 + q0 + q];
        }
        // B tile: 128(j) x 16(q) -> Bs[q][j]
#pragma unroll
        for (int ii = 0; ii < 8; ii++) {
            int idx = t + ii * 256;
            int j = idx >> 4, q = idx & 15;
            Bs[q][j] = Bp[(size_t)j * D2 + q0 + q];
        }
        __syncthreads();
#pragma unroll
        for (int qq = 0; qq < 16; qq++) {
            float4 a  = *(const float4*)&As[qq][tk * 4];
            float4 b0 = *(const float4*)&Bs[qq][tj * 8];
            float4 b1 = *(const float4*)&Bs[qq][tj * 8 + 4];
            float av[4] = {a.x, a.y, a.z, a.w};
            float bv[8] = {b0.x, b0.y, b0.z, b0.w, b1.x, b1.y, b1.z, b1.w};
#pragma unroll
            for (int jj = 0; jj < 8; jj++)
#pragma unroll
                for (int c = 0; c < 4; c++) acc[jj][c] += bv[jj] * av[c];
        }
        __syncthreads();
    }

    float4 bb = *(const float4*)&bias[tk * 4];
#pragma unroll
    for (int jj = 0; jj < 8; jj++) {
        int j = j0 + tj * 8 + jj;
        float4 v = make_float4(acc[jj][0] + bb.x, acc[jj][1] + bb.y,
                               acc[jj][2] + bb.z, acc[jj][3] + bb.w);
        *(float4*)&out[((size_t)i * LSEQ + j) * DK + tk * 4] = v;
    }
}

// ---------------------------------------------------------------------------
extern "C" void kernel_launch(void* const* d_in, const int* in_sizes, int n_in,
                              void* d_out, int out_size)
{
    const float* x1   = (const float*)d_in[0];  // [8,256,512]
    const float* x2   = (const float*)d_in[1];  // [8,256,512]
    const float* w    = (const float*)d_in[2];  // [64,512,512]
    const float* bias = (const float*)d_in[3];  // [64]
    float* out        = (float*)d_out;          // [8,256,256,64]

    float* tmp = nullptr;
    cudaGetSymbolAddress((void**)&tmp, g_tmp);  // host-side query, capture-safe

    dim3 blk(256);
    dim3 g1(NCOL / 64, LSEQ / 128);   // 512 x 2
    dim3 g2(LSEQ / 128, LSEQ);        // 2 x 256

    for (int b = 0; b < NB; b++) {
        stage1_kernel<<<g1, blk>>>(x1 + (size_t)b * LSEQ * D1, w, tmp);
        stage2_kernel<<<g2, blk>>>(tmp, x2 + (size_t)b * LSEQ * D2, bias,
                                   out + (size_t)b * LSEQ * LSEQ * DK);
    }
}

// round 3
// speedup vs baseline: 2.2617x; 2.2617x over previous
#include <cuda_runtime.h>
#include <cuda_bf16.h>
#include <cstdint>

#define BM 128
#define BN 128
#define KC 32
#define RS 40                         // smem row stride in bf16 (80 B, conflict-free ldmatrix)
#define ABYTES (BM * RS * 2)          // 10240
#define SBYTES (2 * ABYTES)           // A + B per stage
#define STAGES 3
#define SMEM_DYN (STAGES * SBYTES)    // 61440
#define NIT 48                        // 3 segments x 16 kc-blocks (K' = 1536)

// ---------------- split-precision operand storage (bf16 hi/lo) ----------------
__device__ __align__(16) __nv_bfloat16 g_x1h[2048 * 512];
__device__ __align__(16) __nv_bfloat16 g_x1l[2048 * 512];
__device__ __align__(16) __nv_bfloat16 g_x2h[2048 * 512];
__device__ __align__(16) __nv_bfloat16 g_x2l[2048 * 512];
__device__ __align__(16) __nv_bfloat16 g_wh[64ull * 512 * 512];   // [k][q][p]
__device__ __align__(16) __nv_bfloat16 g_wl[64ull * 512 * 512];
__device__ __align__(16) __nv_bfloat16 g_tmph[2048ull * 32768];   // [bi][k*512+q]
__device__ __align__(16) __nv_bfloat16 g_tmpl[2048ull * 32768];

// ---------------- asm helpers ----------------
static __device__ __forceinline__ uint32_t s2u(const void* p) {
    uint32_t a;
    asm("{ .reg .u64 t; cvta.to.shared.u64 t, %1; cvt.u32.u64 %0, t; }" : "=r"(a) : "l"(p));
    return a;
}
#define CP16(dst, src) \
    asm volatile("cp.async.cg.shared.global [%0], [%1], 16;" :: "r"(dst), "l"(src) : "memory")
#define CP_COMMIT() asm volatile("cp.async.commit_group;" ::: "memory")
#define CP_WAIT1()  asm volatile("cp.async.wait_group 1;" ::: "memory")
#define LDSM4(r0, r1, r2, r3, addr) \
    asm volatile("ldmatrix.sync.aligned.m8n8.x4.shared.b16 {%0,%1,%2,%3}, [%4];" \
                 : "=r"(r0), "=r"(r1), "=r"(r2), "=r"(r3) : "r"(addr))
#define MMA16816(d, a, b0, b1) \
    asm volatile("mma.sync.aligned.m16n8k16.row.col.f32.bf16.bf16.f32 " \
                 "{%0,%1,%2,%3}, {%4,%5,%6,%7}, {%8,%9}, {%0,%1,%2,%3};" \
                 : "+f"((d)[0]), "+f"((d)[1]), "+f"((d)[2]), "+f"((d)[3]) \
                 : "r"((a)[0]), "r"((a)[1]), "r"((a)[2]), "r"((a)[3]), "r"(b0), "r"(b1))

// shared GEMM core: pipeline + mma loop. Caller provides per-thread load offsets
// (elements) and segment base pointers. acc[4][4][4] accumulated across all 48 its.
#define GEMM_CORE(SEGA0, SEGA2, SEGB0, SEGB1)                                        \
    {                                                                                \
        /* prologue */                                                               \
        _issue(0, SEGA0, SEGB0);                                                     \
        _issue(1, SEGA0, SEGB0);                                                     \
        _Pragma("unroll 1")                                                          \
        for (int it = 0; it < NIT; it++) {                                           \
            CP_WAIT1();                                                              \
            __syncthreads();                                                         \
            int nx = it + 2;                                                         \
            if (nx < NIT) {                                                          \
                int seg = nx >> 4;                                                   \
                const __nv_bfloat16* pa = (seg == 2) ? SEGA2 : SEGA0;                \
                const __nv_bfloat16* pb = (seg == 1) ? SEGB1 : SEGB0;                \
                _issue(nx, pa, pb);                                                  \
            } else {                                                                 \
                CP_COMMIT();                                                         \
            }                                                                        \
            uint32_t sb = sbase + (it % STAGES) * SBYTES;                            \
            uint32_t aBase = sb + (wm + lrow) * (RS * 2) + lh * 16;                  \
            uint32_t bBase = sb + ABYTES + (wn + lrow) * (RS * 2) + lh * 16;         \
            _Pragma("unroll")                                                        \
            for (int kk = 0; kk < 2; kk++) {                                         \
                uint32_t af[4][4], br[2][4];                                         \
                _Pragma("unroll")                                                    \
                for (int mi = 0; mi < 4; mi++)                                       \
                    LDSM4(af[mi][0], af[mi][1], af[mi][2], af[mi][3],                \
                          aBase + mi * 16 * (RS * 2) + kk * 32);                     \
                _Pragma("unroll")                                                    \
                for (int nb = 0; nb < 2; nb++)                                       \
                    LDSM4(br[nb][0], br[nb][1], br[nb][2], br[nb][3],                \
                          bBase + nb * 16 * (RS * 2) + kk * 32);                     \
                _Pragma("unroll")                                                    \
                for (int mi = 0; mi < 4; mi++)                                       \
                    _Pragma("unroll")                                                \
                    for (int ni = 0; ni < 4; ni++)                                   \
                        MMA16816(acc[mi][ni], af[mi],                                \
                                 br[ni >> 1][ni & 1], br[ni >> 1][(ni & 1) + 2]);    \
            }                                                                        \
        }                                                                            \
    }

// ---------------- preprocessing ----------------
__global__ void __launch_bounds__(256) split_x_kernel(const float* __restrict__ x,
                                                      __nv_bfloat16* __restrict__ h,
                                                      __nv_bfloat16* __restrict__ lo) {
    int i = blockIdx.x * 256 + threadIdx.x;
    float v = x[i];
    __nv_bfloat16 hb = __float2bfloat16_rn(v);
    h[i] = hb;
    lo[i] = __float2bfloat16_rn(v - __bfloat162float(hb));
}

// W[k][p][q] -> g_wh/g_wl[k][q][p]
__global__ void __launch_bounds__(256) splitW_kernel(const float* __restrict__ w) {
    __shared__ float tile[32][33];
    int k = blockIdx.z, p0 = blockIdx.y * 32, q0 = blockIdx.x * 32;
    int tx = threadIdx.x & 31, ty = threadIdx.x >> 5;
    const float* src = w + ((size_t)k * 512 + p0) * 512 + q0;
#pragma unroll
    for (int r = 0; r < 32; r += 8) tile[ty + r][tx] = src[(size_t)(ty + r) * 512 + tx];
    __syncthreads();
    size_t dof = ((size_t)k * 512 + q0) * 512 + p0;
#pragma unroll
    for (int r = 0; r < 32; r += 8) {
        float v = tile[tx][ty + r];
        __nv_bfloat16 hb = __float2bfloat16_rn(v);
        g_wh[dof + (size_t)(ty + r) * 512 + tx] = hb;
        g_wl[dof + (size_t)(ty + r) * 512 + tx] =
            __float2bfloat16_rn(v - __bfloat162float(hb));
    }
}

// ---------------- stage 1: tmp[bi, k*512+q] = sum_p x1[bi,p] W[k,p,q] ----------------
// C[2048, 32768] = A[2048,512] * B(col-major rows n=(k,q), k-contig p)
__global__ void __launch_bounds__(256, 1) stage1_kernel() {
    extern __shared__ __align__(16) char sm[];
    uint32_t sbase = s2u(sm);
    int t = threadIdx.x, l = t & 31, w = t >> 5;
    int m0 = blockIdx.x * BM, n0 = blockIdx.y * BN;
    int wm = (w >> 2) * 64, wn = (w & 3) * 32;
    int lrow = l & 15, lh = l >> 4;

    uint32_t aOff[2], bOff[2], aDst[2], bDst[2];
#pragma unroll
    for (int i = 0; i < 2; i++) {
        int o = t * 2 + i, r = o >> 2, c = o & 3;
        aOff[i] = (uint32_t)(m0 + r) * 512 + c * 8;
        int ng = n0 + r, kf = ng >> 9, q = ng & 511;
        bOff[i] = (uint32_t)(kf * 512 + q) * 512 + c * 8;
        aDst[i] = r * (RS * 2) + c * 16;
        bDst[i] = ABYTES + r * (RS * 2) + c * 16;
    }
    float acc[4][4][4];
#pragma unroll
    for (int a = 0; a < 4; a++)
#pragma unroll
        for (int b = 0; b < 4; b++)
#pragma unroll
            for (int c = 0; c < 4; c++) acc[a][b][c] = 0.f;

    auto _issue = [&](int it, const __nv_bfloat16* pa, const __nv_bfloat16* pb) {
        int kb = it & 15;
        uint32_t sb = sbase + (it % STAGES) * SBYTES;
#pragma unroll
        for (int i = 0; i < 2; i++) {
            CP16(sb + aDst[i], pa + aOff[i] + kb * KC);
            CP16(sb + bDst[i], pb + bOff[i] + kb * KC);
        }
        CP_COMMIT();
    };

    GEMM_CORE(g_x1h, g_x1l, g_wh, g_wl)

    // epilogue: split C into bf16 hi/lo -> g_tmph/g_tmpl
#pragma unroll
    for (int mi = 0; mi < 4; mi++) {
        int r0 = m0 + wm + mi * 16 + (l >> 2);
#pragma unroll
        for (int ni = 0; ni < 4; ni++) {
            int c = n0 + wn + ni * 8 + (l & 3) * 2;
#pragma unroll
            for (int hrow = 0; hrow < 2; hrow++) {
                size_t idx = (size_t)(r0 + hrow * 8) * 32768 + c;
                float v0 = acc[mi][ni][hrow * 2], v1 = acc[mi][ni][hrow * 2 + 1];
                __nv_bfloat162 hh, ll;
                hh.x = __float2bfloat16_rn(v0);
                hh.y = __float2bfloat16_rn(v1);
                ll.x = __float2bfloat16_rn(v0 - __bfloat162float(hh.x));
                ll.y = __float2bfloat16_rn(v1 - __bfloat162float(hh.y));
                *(__nv_bfloat162*)&g_tmph[idx] = hh;
                *(__nv_bfloat162*)&g_tmpl[idx] = ll;
            }
        }
    }
}

// ---------------- stage 2: out[b,i0+il,j,k] = sum_q tmp[.,k,q] x2[b,j,q] + bias ------
// per CTA: M=128 j-rows, N=128 cols (2 il x 64 k), K'=1536
__global__ void __launch_bounds__(256, 1) stage2_kernel(const float* __restrict__ bias,
                                                        float* __restrict__ out) {
    extern __shared__ __align__(16) char sm[];
    __shared__ float s_bias[64];
    uint32_t sbase = s2u(sm);
    int t = threadIdx.x, l = t & 31, w = t >> 5;
    int bz = blockIdx.z;
    int b = bz >> 6, i0 = (bz & 63) * 4;
    int j0 = blockIdx.x * BM, n0 = blockIdx.y * BN;
    int wm = (w >> 2) * 64, wn = (w & 3) * 32;
    int lrow = l & 15, lh = l >> 4;
    if (t < 64) s_bias[t] = bias[t];

    uint32_t aOff[2], bOff[2], aDst[2], bDst[2];
#pragma unroll
    for (int i = 0; i < 2; i++) {
        int o = t * 2 + i, r = o >> 2, c = o & 3;
        aOff[i] = (uint32_t)(b * 256 + j0 + r) * 512 + c * 8;
        int ng = n0 + r, il = ng >> 6, k = ng & 63;
        bOff[i] = (uint32_t)(b * 256 + i0 + il) * 32768 + k * 512 + c * 8;
        aDst[i] = r * (RS * 2) + c * 16;
        bDst[i] = ABYTES + r * (RS * 2) + c * 16;
    }
    float acc[4][4][4];
#pragma unroll
    for (int a = 0; a < 4; a++)
#pragma unroll
        for (int bb = 0; bb < 4; bb++)
#pragma unroll
            for (int c = 0; c < 4; c++) acc[a][bb][c] = 0.f;

    auto _issue = [&](int it, const __nv_bfloat16* pa, const __nv_bfloat16* pb) {
        int kb = it & 15;
        uint32_t sb = sbase + (it % STAGES) * SBYTES;
#pragma unroll
        for (int i = 0; i < 2; i++) {
            CP16(sb + aDst[i], pa + aOff[i] + kb * KC);
            CP16(sb + bDst[i], pb + bOff[i] + kb * KC);
        }
        CP_COMMIT();
    };

    GEMM_CORE(g_x2h, g_x2l, g_tmph, g_tmpl)

    // epilogue: add bias, write fp32 out[b, i0+il, j, k]
#pragma unroll
    for (int mi = 0; mi < 4; mi++) {
        int j = j0 + wm + mi * 16 + (l >> 2);
#pragma unroll
        for (int ni = 0; ni < 4; ni++) {
            int c = n0 + wn + ni * 8 + (l & 3) * 2;
            int il = c >> 6, k = c & 63;
            float bk0 = s_bias[k], bk1 = s_bias[k + 1];
#pragma unroll
            for (int hrow = 0; hrow < 2; hrow++) {
                size_t idx = ((size_t)(b * 256 + i0 + il) * 256 + j + hrow * 8) * 64 + k;
                float2 v = make_float2(acc[mi][ni][hrow * 2] + bk0,
                                       acc[mi][ni][hrow * 2 + 1] + bk1);
                *(float2*)&out[idx] = v;
            }
        }
    }
}

// ---------------- host ----------------
extern "C" void kernel_launch(void* const* d_in, const int* in_sizes, int n_in,
                              void* d_out, int out_size)
{
    const float* x1   = (const float*)d_in[0];
    const float* x2   = (const float*)d_in[1];
    const float* w    = (const float*)d_in[2];
    const float* bias = (const float*)d_in[3];
    float* out        = (float*)d_out;

    cudaFuncSetAttribute(stage1_kernel, cudaFuncAttributeMaxDynamicSharedMemorySize, SMEM_DYN);
    cudaFuncSetAttribute(stage2_kernel, cudaFuncAttributeMaxDynamicSharedMemorySize, SMEM_DYN);

    void *px1h, *px1l, *px2h, *px2l;
    cudaGetSymbolAddress(&px1h, g_x1h);
    cudaGetSymbolAddress(&px1l, g_x1l);
    cudaGetSymbolAddress(&px2h, g_x2h);
    cudaGetSymbolAddress(&px2l, g_x2l);

    split_x_kernel<<<4096, 256>>>(x1, (__nv_bfloat16*)px1h, (__nv_bfloat16*)px1l);
    split_x_kernel<<<4096, 256>>>(x2, (__nv_bfloat16*)px2h, (__nv_bfloat16*)px2l);
    splitW_kernel<<<dim3(16, 16, 64), 256>>>(w);

    stage1_kernel<<<dim3(16, 256), 256, SMEM_DYN>>>();
    stage2_kernel<<<dim3(2, 2, 512), 256, SMEM_DYN>>>(bias, out);
}